// round 1
// baseline (speedup 1.0000x reference)
#include <cuda_runtime.h>
#include <math.h>

// Problem constants
#define NNODES 32768
#define DIN    128
#define DD     256
#define D2     512
#define EDGES  131072
#define BGR    256
#define EPG    512
#define NPG    128
#define NRES   256
#define BN_EPS 1e-5f

// Output layout (float32, 524288 elems):
// [0:131072)       causal_ei (2 x 65536)
// [131072:196608)  causal_w
// [196608:327680)  conf_ei (2 x 65536)
// [327680:393216)  conf_w
// [393216:524288)  pred
#define OFF_CEI   0
#define OFF_CW    131072
#define OFF_DEI   196608
#define OFF_DW    327680
#define OFF_PRED  393216

// ---------------- scratch (device globals; no allocation) ----------------
__device__ float g_h1[NNODES * DIN];    // 16 MB
__device__ float g_z [NNODES * D2];     // 64 MB (z, then z2)
__device__ float g_o1[NNODES * DD];     // 32 MB (gin1 out, then gin2 out)
__device__ float g_h2[NNODES * DD];     // 32 MB
__device__ float g_part[2 * 256 * 512]; // BN partial sums (deterministic)
__device__ float g_scale[512];
__device__ float g_shift[512];
__device__ float g_sa[NNODES];
__device__ float g_sc[NNODES];

// ---------------- per-graph aggregation: h = in' + segsum(in'[row] -> col) ----------------
// mode 0: in' = in (identity). mode 1: in' = relu(in*scale+shift) + vemb.
// grid: (BGR, dimtot/64), block: 64 threads (one per dim in the slice).
__global__ void agg_kernel(const float* __restrict__ in, float* __restrict__ outh,
                           const int* __restrict__ ei, int dimtot, int mode,
                           const float* __restrict__ scale, const float* __restrict__ shift,
                           const float* __restrict__ vemb)
{
    __shared__ float agg[NPG * 64];
    __shared__ int   se[2 * EPG];
    const int g  = blockIdx.x;
    const int d0 = blockIdx.y * 64;
    const int t  = threadIdx.x;

    for (int e = t; e < EPG; e += 64) {
        se[e]       = ei[g * EPG + e];          // row (src)
        se[EPG + e] = ei[EDGES + g * EPG + e];  // col (dst)
    }
    for (int i = t; i < NPG * 64; i += 64) agg[i] = 0.f;
    __syncthreads();

    const int nb = g * NPG;
    const int d  = d0 + t;
    float sc_ = 0.f, sh_ = 0.f, ve = 0.f;
    if (mode) { sc_ = scale[d]; sh_ = shift[d]; ve = vemb[d]; }

    for (int e = 0; e < EPG; ++e) {
        const int r = se[e] - nb;
        const int c = se[EPG + e] - nb;
        float v = in[(size_t)(nb + r) * dimtot + d];
        if (mode) v = fmaxf(v * sc_ + sh_, 0.f) + ve;
        agg[c * 64 + t] += v;
    }
    __syncthreads();

    for (int n = 0; n < NPG; ++n) {
        float v = in[(size_t)(nb + n) * dimtot + d];
        if (mode) v = fmaxf(v * sc_ + sh_, 0.f) + ve;
        outh[(size_t)(nb + n) * dimtot + d] = v + agg[n * 64 + t];
    }
}

// ---------------- fp32 tiled GEMM: C = A' @ B + bias ----------------
// A' = A (tsc==null) or relu(A*tsc[k]+tsh[k]) applied per K-column.
// Tiles: BM=128, BN=64, BK=16; 256 threads; 8x4 per-thread register tile.
#define BM  128
#define BNT 64
#define BK  16
__global__ __launch_bounds__(256)
void gemm_kernel(const float* __restrict__ A, const float* __restrict__ Bm,
                 const float* __restrict__ bias, float* __restrict__ C,
                 int K, int Nc,
                 const float* __restrict__ tsc, const float* __restrict__ tsh)
{
    __shared__ float As[BK * BM];
    __shared__ float Bs[BK * BNT];
    const int tid = threadIdx.x;
    const int tx  = tid & 15;   // N dir
    const int ty  = tid >> 4;   // M dir
    const int n0  = blockIdx.x * BNT;
    const int m0  = blockIdx.y * BM;

    float acc[8][4];
#pragma unroll
    for (int i = 0; i < 8; i++)
#pragma unroll
        for (int j = 0; j < 4; j++) acc[i][j] = 0.f;

    for (int k0 = 0; k0 < K; k0 += BK) {
        // A tile (128x16), stored transposed As[k][m]
#pragma unroll
        for (int i = 0; i < 2; ++i) {
            const int idx = tid * 2 + i;       // 0..511
            const int m   = idx >> 2;          // 0..127
            const int kq  = (idx & 3) * 4;     // 0,4,8,12
            float4 a = *(const float4*)(A + (size_t)(m0 + m) * K + k0 + kq);
            if (tsc) {
                const int kk = k0 + kq;
                a.x = fmaxf(a.x * tsc[kk + 0] + tsh[kk + 0], 0.f);
                a.y = fmaxf(a.y * tsc[kk + 1] + tsh[kk + 1], 0.f);
                a.z = fmaxf(a.z * tsc[kk + 2] + tsh[kk + 2], 0.f);
                a.w = fmaxf(a.w * tsc[kk + 3] + tsh[kk + 3], 0.f);
            }
            As[(kq + 0) * BM + m] = a.x;
            As[(kq + 1) * BM + m] = a.y;
            As[(kq + 2) * BM + m] = a.z;
            As[(kq + 3) * BM + m] = a.w;
        }
        // B tile (16x64)
        {
            const int k  = tid >> 4;
            const int nq = (tid & 15) * 4;
            *(float4*)(Bs + k * BNT + nq) =
                *(const float4*)(Bm + (size_t)(k0 + k) * Nc + n0 + nq);
        }
        __syncthreads();

#pragma unroll
        for (int kk = 0; kk < BK; ++kk) {
            float a[8], b[4];
            *(float4*)(a)     = *(const float4*)(As + kk * BM + ty * 8);
            *(float4*)(a + 4) = *(const float4*)(As + kk * BM + ty * 8 + 4);
            *(float4*)(b)     = *(const float4*)(Bs + kk * BNT + tx * 4);
#pragma unroll
            for (int i = 0; i < 8; i++)
#pragma unroll
                for (int j = 0; j < 4; j++)
                    acc[i][j] = fmaf(a[i], b[j], acc[i][j]);
        }
        __syncthreads();
    }

    float bb[4];
#pragma unroll
    for (int j = 0; j < 4; j++) bb[j] = bias[n0 + tx * 4 + j];
#pragma unroll
    for (int i = 0; i < 8; i++) {
        const int m = m0 + ty * 8 + i;
        float4 v = make_float4(acc[i][0] + bb[0], acc[i][1] + bb[1],
                               acc[i][2] + bb[2], acc[i][3] + bb[3]);
        *(float4*)(C + (size_t)m * Nc + n0 + tx * 4) = v;
    }
}

// ---------------- BN stats: deterministic two-level column reduction ----------------
__global__ void stats_kernel(const float* __restrict__ X, int C, float* __restrict__ part)
{
    const int blk = blockIdx.x;      // 0..255
    const int t   = threadIdx.x;     // C threads
    const int r0  = blk * (NNODES / 256);
    float s = 0.f, ss = 0.f;
    for (int r = 0; r < NNODES / 256; ++r) {
        const float v = X[(size_t)(r0 + r) * C + t];
        s += v; ss += v * v;
    }
    part[blk * C + t]             = s;
    part[256 * 512 + blk * C + t] = ss;
}

__global__ void finalize_kernel(const float* __restrict__ gg, const float* __restrict__ be,
                                int C, const float* __restrict__ part,
                                float* __restrict__ scale, float* __restrict__ shift)
{
    const int t = threadIdx.x;   // C threads
    float s = 0.f, ss = 0.f;
    for (int b = 0; b < 256; ++b) {
        s  += part[b * C + t];
        ss += part[256 * 512 + b * C + t];
    }
    const float mu  = s / (float)NNODES;
    const float var = ss / (float)NNODES - mu * mu;
    const float rs  = rsqrtf(var + BN_EPS);
    const float sc  = gg[t] * rs;
    scale[t] = sc;
    shift[t] = be[t] - mu * sc;
}

// ---------------- per-node edge-logit halves: sa = bn(xn)·Wl[:256], sc = bn(xn)·Wl[256:] ----------------
__global__ void nodedot_kernel(const float* __restrict__ Xn, const float* __restrict__ Wl,
                               const float* __restrict__ scale, const float* __restrict__ shift,
                               float* __restrict__ sa_o, float* __restrict__ sc_o)
{
    const int w = threadIdx.x >> 5;
    const int l = threadIdx.x & 31;
    const int n = blockIdx.x * 8 + w;
    float sa = 0.f, sc = 0.f;
#pragma unroll
    for (int i = 0; i < 8; ++i) {
        const int d = l + i * 32;
        const float v = Xn[(size_t)n * DD + d] * scale[d] + shift[d];  // no relu on final BN
        sa = fmaf(v, Wl[d], sa);
        sc = fmaf(v, Wl[DD + d], sc);
    }
#pragma unroll
    for (int o = 16; o; o >>= 1) {
        sa += __shfl_down_sync(0xffffffffu, sa, o);
        sc += __shfl_down_sync(0xffffffffu, sc, o);
    }
    if (l == 0) { sa_o[n] = sa; sc_o[n] = sc; }
}

// ---------------- per-edge prediction ----------------
__global__ void pred_kernel(const int* __restrict__ ei, const float* __restrict__ bl,
                            const float* __restrict__ sa, const float* __restrict__ sc,
                            float* __restrict__ out)
{
    const int e = blockIdx.x * 256 + threadIdx.x;
    out[OFF_PRED + e] = sa[ei[e]] + sc[ei[EDGES + e]] + bl[0];
}

// ---------------- per-graph stable descending sort + output scatter ----------------
__device__ __forceinline__ unsigned ordered_f32(float f)
{
    unsigned u = __float_as_uint(f);
    return (u & 0x80000000u) ? ~u : (u | 0x80000000u);
}

__global__ void sort_kernel(const int* __restrict__ ei, float* __restrict__ out)
{
    __shared__ unsigned long long keys[EPG];
    const int g = blockIdx.x;
    const int t = threadIdx.x;   // 256 threads
    const float* pred = out + OFF_PRED + (size_t)g * EPG;

    // key: value-descending, index-ascending ties => ascending sort of (~ordered(f), idx)
    for (int j = t; j < EPG; j += 256) {
        const unsigned u = ordered_f32(pred[j]);
        keys[j] = ((unsigned long long)(~u) << 32) | (unsigned)j;
    }
    __syncthreads();

    for (int k = 2; k <= EPG; k <<= 1) {
        for (int j = k >> 1; j > 0; j >>= 1) {
            for (int i = t; i < EPG; i += 256) {
                const int ixj = i ^ j;
                if (ixj > i) {
                    const bool up = ((i & k) == 0);
                    unsigned long long a = keys[i], b = keys[ixj];
                    if ((a > b) == up) { keys[i] = b; keys[ixj] = a; }
                }
            }
            __syncthreads();
        }
    }

    for (int j = t; j < EPG; j += 256) {
        const int   idx = (int)(keys[j] & 0xffffffffu);
        const float p   = pred[idx];
        const int   s   = ei[g * EPG + idx];
        const int   dst = ei[EDGES + g * EPG + idx];
        if (j < NRES) {
            const int o = g * NRES + j;
            out[OFF_CEI + o]         = (float)s;
            out[OFF_CEI + 65536 + o] = (float)dst;
            out[OFF_CW + o]          = p;
        } else {
            const int o = g * NRES + (j - NRES);
            out[OFF_DEI + o]         = (float)s;
            out[OFF_DEI + 65536 + o] = (float)dst;
            out[OFF_DW + o]          = -p;
        }
    }
}

// ---------------- launch ----------------
extern "C" void kernel_launch(void* const* d_in, const int* in_sizes, int n_in,
                              void* d_out, int out_size)
{
    const float* x    = (const float*)d_in[0];
    const int*   ei   = (const int*)  d_in[1];
    // d_in[2] = batch (unused: vemb is identical for all graphs)
    const float* vemb = (const float*)d_in[3];
    const float* W1a  = (const float*)d_in[4];
    const float* b1a  = (const float*)d_in[5];
    const float* g1a  = (const float*)d_in[6];
    const float* be1a = (const float*)d_in[7];
    const float* W1b  = (const float*)d_in[8];
    const float* b1b  = (const float*)d_in[9];
    const float* g1   = (const float*)d_in[10];
    const float* be1  = (const float*)d_in[11];
    const float* W2a  = (const float*)d_in[12];
    const float* b2a  = (const float*)d_in[13];
    const float* g2a  = (const float*)d_in[14];
    const float* be2a = (const float*)d_in[15];
    const float* W2b  = (const float*)d_in[16];
    const float* b2b  = (const float*)d_in[17];
    const float* g2   = (const float*)d_in[18];
    const float* be2  = (const float*)d_in[19];
    const float* Wl   = (const float*)d_in[20];
    const float* bl   = (const float*)d_in[21];
    float* out = (float*)d_out;

    float *ph1, *pz, *po1, *ph2, *ppart, *pscale, *pshift, *psa, *psc;
    cudaGetSymbolAddress((void**)&ph1,    g_h1);
    cudaGetSymbolAddress((void**)&pz,     g_z);
    cudaGetSymbolAddress((void**)&po1,    g_o1);
    cudaGetSymbolAddress((void**)&ph2,    g_h2);
    cudaGetSymbolAddress((void**)&ppart,  g_part);
    cudaGetSymbolAddress((void**)&pscale, g_scale);
    cudaGetSymbolAddress((void**)&pshift, g_shift);
    cudaGetSymbolAddress((void**)&psa,    g_sa);
    cudaGetSymbolAddress((void**)&psc,    g_sc);

    // Layer 1
    agg_kernel<<<dim3(BGR, DIN / 64), 64>>>(x, ph1, ei, DIN, 0, nullptr, nullptr, nullptr);
    gemm_kernel<<<dim3(D2 / BNT, NNODES / BM), 256>>>(ph1, W1a, b1a, pz, DIN, D2, nullptr, nullptr);
    stats_kernel<<<256, 512>>>(pz, 512, ppart);
    finalize_kernel<<<1, 512>>>(g1a, be1a, 512, ppart, pscale, pshift);
    gemm_kernel<<<dim3(DD / BNT, NNODES / BM), 256>>>(pz, W1b, b1b, po1, D2, DD, pscale, pshift);
    stats_kernel<<<256, 256>>>(po1, 256, ppart);
    finalize_kernel<<<1, 256>>>(g1, be1, 256, ppart, pscale, pshift);

    // Layer 2 (post = relu(bn(o1)) + vemb, fused into aggregation)
    agg_kernel<<<dim3(BGR, DD / 64), 64>>>(po1, ph2, ei, DD, 1, pscale, pshift, vemb);
    gemm_kernel<<<dim3(D2 / BNT, NNODES / BM), 256>>>(ph2, W2a, b2a, pz, DD, D2, nullptr, nullptr);
    stats_kernel<<<256, 512>>>(pz, 512, ppart);
    finalize_kernel<<<1, 512>>>(g2a, be2a, 512, ppart, pscale, pshift);
    gemm_kernel<<<dim3(DD / BNT, NNODES / BM), 256>>>(pz, W2b, b2b, po1, D2, DD, pscale, pshift);
    stats_kernel<<<256, 256>>>(po1, 256, ppart);
    finalize_kernel<<<1, 256>>>(g2, be2, 256, ppart, pscale, pshift);

    // Edge scores + per-graph stable top-k split
    nodedot_kernel<<<NNODES / 8, 256>>>(po1, Wl, pscale, pshift, psa, psc);
    pred_kernel<<<EDGES / 256, 256>>>(ei, bl, psa, psc, out);
    sort_kernel<<<BGR, 256>>>(ei, out);
}